// round 2
// baseline (speedup 1.0000x reference)
#include <cuda_runtime.h>

// ---------------------------------------------------------------------------
// Complex MHA, fp32 with packed f32x2 FMA inner loops.
// Stage 1: complex input projections (Q,K,V), head-split layout (B,H,N,64)
// Stage 2: fused attention per (b,h): scores (conj), exp(|s|/8), PV, no max
// Stage 3: complex output projection, interleaved (re,im) output
// ---------------------------------------------------------------------------

#define H_HEADS 8
#define NTOK    2048
#define KDIM    512
#define NDIM    512

typedef unsigned long long u64;

__device__ __forceinline__ u64 pk2(float x, float y) {
    u64 r; asm("mov.b64 %0,{%1,%2};" : "=l"(r) : "f"(x), "f"(y)); return r;
}
__device__ __forceinline__ void fma2(u64 &d, u64 a, u64 b) {
    asm("fma.rn.f32x2 %0,%1,%2,%0;" : "+l"(d) : "l"(a), "l"(b));
}
__device__ __forceinline__ float2 up2(u64 v) {
    float2 r; asm("mov.b64 {%0,%1},%2;" : "=f"(r.x), "=f"(r.y) : "l"(v)); return r;
}

// Scratch: projected Q/K/V in (B*H, N, 64) layout; attention out in (B*N, 512)
__device__ float g_qr[16 * 2048 * 64];
__device__ float g_qi[16 * 2048 * 64];
__device__ float g_kr[16 * 2048 * 64];
__device__ float g_ki[16 * 2048 * 64];
__device__ float g_vr[16 * 2048 * 64];
__device__ float g_vi[16 * 2048 * 64];
__device__ float g_or[4096 * 512];
__device__ float g_oi[4096 * 512];

// ---------------------------------------------------------------------------
// Fused complex NT GEMM:  Y = (Ar + iAi) @ (Br + iBi)^T   (B stored (out,in))
//   yr = Ar Br^T - Ai Bi^T ;  yi = Ar Bi^T + Ai Br^T
// MODE 0: write head-split (b, h, n, d) into Or_/Oi_
// MODE 1: write interleaved (yr, yi) pairs into Or_ (final output)
// M = gridDim.y*64 (=4096), N = 512, K = 512
// ---------------------------------------------------------------------------
template<int MODE>
__global__ void __launch_bounds__(256, 2) cgemm_nt(
    const float* __restrict__ Ar, const float* __restrict__ Ai,
    const float* __restrict__ Br, const float* __restrict__ Bi,
    float* __restrict__ Or_, float* __restrict__ Oi_)
{
    __shared__ float sAr[16][68], sAi[16][68], sBr[16][68], sBi[16][68];

    const int tid = threadIdx.x;
    const int tx = tid & 15, ty = tid >> 4;
    const int row = tid >> 2, kq = tid & 3;
    const int mBase = blockIdx.y * 64, nBase = blockIdx.x * 64;

    u64 cre[4][2], cim[4][2];
#pragma unroll
    for (int i = 0; i < 4; i++) {
#pragma unroll
        for (int j = 0; j < 2; j++) { cre[i][j] = 0ull; cim[i][j] = 0ull; }
    }

    const int aoff = (mBase + row) * KDIM + kq * 4;
    const int boff = (nBase + row) * KDIM + kq * 4;

    for (int kc = 0; kc < KDIM; kc += 16) {
        float4 a_r = *(const float4*)(Ar + aoff + kc);
        float4 a_i = *(const float4*)(Ai + aoff + kc);
        float4 b_r = *(const float4*)(Br + boff + kc);
        float4 b_i = *(const float4*)(Bi + boff + kc);
#pragma unroll
        for (int j = 0; j < 4; j++) {
            sAr[kq * 4 + j][row] = ((float*)&a_r)[j];
            sAi[kq * 4 + j][row] = ((float*)&a_i)[j];
            sBr[kq * 4 + j][row] = ((float*)&b_r)[j];
            sBi[kq * 4 + j][row] = ((float*)&b_i)[j];
        }
        __syncthreads();
#pragma unroll
        for (int k = 0; k < 16; k++) {
            float4 ar = *(const float4*)&sAr[k][ty * 4];
            float4 ai = *(const float4*)&sAi[k][ty * 4];
            ulonglong2 br = *(const ulonglong2*)&sBr[k][tx * 4];
            ulonglong2 bi = *(const ulonglong2*)&sBi[k][tx * 4];
#pragma unroll
            for (int i = 0; i < 4; i++) {
                float arv = ((float*)&ar)[i], aiv = ((float*)&ai)[i];
                u64 par  = pk2(arv,  arv);
                u64 pai  = pk2(aiv,  aiv);
                u64 pnai = pk2(-aiv, -aiv);
                fma2(cre[i][0], par,  br.x); fma2(cre[i][0], pnai, bi.x);
                fma2(cre[i][1], par,  br.y); fma2(cre[i][1], pnai, bi.y);
                fma2(cim[i][0], par,  bi.x); fma2(cim[i][0], pai,  br.x);
                fma2(cim[i][1], par,  bi.y); fma2(cim[i][1], pai,  br.y);
            }
        }
        __syncthreads();
    }

#pragma unroll
    for (int i = 0; i < 4; i++) {
        const int m = mBase + ty * 4 + i;
        float2 r0 = up2(cre[i][0]), r1 = up2(cre[i][1]);
        float2 i0 = up2(cim[i][0]), i1 = up2(cim[i][1]);
        if (MODE == 0) {
            const int b = m >> 11, n = m & 2047;
            const int h = nBase >> 6;          // whole 64-col block is one head
            const int d0 = tx * 4;
            size_t idx = ((size_t)((b * H_HEADS + h) * NTOK + n)) * 64 + d0;
            *(float4*)(Or_ + idx) = make_float4(r0.x, r0.y, r1.x, r1.y);
            *(float4*)(Oi_ + idx) = make_float4(i0.x, i0.y, i1.x, i1.y);
        } else {
            const int o0 = nBase + tx * 4;
            size_t base = ((size_t)m * NDIM + o0) * 2;
            *(float4*)(Or_ + base)     = make_float4(r0.x, i0.x, r0.y, i0.y);
            *(float4*)(Or_ + base + 4) = make_float4(r1.x, i1.x, r1.y, i1.y);
        }
    }
}

// ---------------------------------------------------------------------------
// Fused complex attention. Grid: (NQ/64, B*H). Block: 256 threads.
//   s_re = qr kr + qi ki ; s_im = qi kr - qr ki   (Q @ conj(K)^T)
//   p = exp(|s| / 8), no running max (scores are small by construction)
//   o = (sum p V) / (sum p)
// Output written directly in (B, N, H*64) concat layout.
// ---------------------------------------------------------------------------
__global__ void __launch_bounds__(256, 1) attn_kernel(
    const float* __restrict__ Qr, const float* __restrict__ Qi,
    const float* __restrict__ Kr, const float* __restrict__ Ki,
    const float* __restrict__ Vr, const float* __restrict__ Vi,
    float* __restrict__ Or_, float* __restrict__ Oi_)
{
    extern __shared__ float smemf[];
    float* sQr = smemf;
    float* sQi = sQr + 64 * 68;
    float* sKr = sQi + 64 * 68;
    float* sKi = sKr + 64 * 68;
    float* sVr = sKi + 64 * 68;
    float* sVi = sVr + 64 * 68;
    float* sP  = sKr;   // alias: P overwrites K after scores are consumed

    const int tid = threadIdx.x;
    const int tx = tid & 15, ty = tid >> 4;
    const int lr = tid >> 4;   // 0..15 : row within a 16-row chunk
    const int lc = tid & 15;   // 0..15 : which float4 of the 64-wide row
    const int bh = blockIdx.y;
    const int q0 = blockIdx.x * 64;

    const float* Qrb = Qr + ((size_t)bh * NTOK + q0) * 64;
    const float* Qib = Qi + ((size_t)bh * NTOK + q0) * 64;
    const float* Krb = Kr + (size_t)bh * NTOK * 64;
    const float* Kib = Ki + (size_t)bh * NTOK * 64;
    const float* Vrb = Vr + (size_t)bh * NTOK * 64;
    const float* Vib = Vi + (size_t)bh * NTOK * 64;

    // Load full 64x64 Q tile, transposed to [d][q]
#pragma unroll
    for (int c = 0; c < 4; c++) {
        const int r = c * 16 + lr;
        float4 a = *(const float4*)(Qrb + r * 64 + lc * 4);
        float4 b = *(const float4*)(Qib + r * 64 + lc * 4);
#pragma unroll
        for (int j = 0; j < 4; j++) {
            sQr[(lc * 4 + j) * 68 + r] = ((float*)&a)[j];
            sQi[(lc * 4 + j) * 68 + r] = ((float*)&b)[j];
        }
    }

    u64 ore[4][2], oim[4][2];
    float lsum[4];
#pragma unroll
    for (int i = 0; i < 4; i++) {
        lsum[i] = 0.f;
#pragma unroll
        for (int j = 0; j < 2; j++) { ore[i][j] = 0ull; oim[i][j] = 0ull; }
    }

    for (int t = 0; t < NTOK / 64; t++) {
        __syncthreads();   // prev PV readers done (and Q loaded on t=0)
        // Load full 64x64 K (transposed [d][k]) and V (row-major [k][d]) tiles
#pragma unroll
        for (int c = 0; c < 4; c++) {
            const int r = c * 16 + lr;
            const int goff = (t * 64 + r) * 64 + lc * 4;
            float4 kr4 = *(const float4*)(Krb + goff);
            float4 ki4 = *(const float4*)(Kib + goff);
            float4 vr4 = *(const float4*)(Vrb + goff);
            float4 vi4 = *(const float4*)(Vib + goff);
#pragma unroll
            for (int j = 0; j < 4; j++) {
                sKr[(lc * 4 + j) * 68 + r] = ((float*)&kr4)[j];
                sKi[(lc * 4 + j) * 68 + r] = ((float*)&ki4)[j];
            }
            *(float4*)&sVr[r * 68 + lc * 4] = vr4;
            *(float4*)&sVi[r * 68 + lc * 4] = vi4;
        }
        __syncthreads();

        u64 sre[4][2], sim[4][2];
#pragma unroll
        for (int i = 0; i < 4; i++) {
#pragma unroll
            for (int j = 0; j < 2; j++) { sre[i][j] = 0ull; sim[i][j] = 0ull; }
        }

#pragma unroll 8
        for (int d = 0; d < 64; d++) {
            float4 qr = *(const float4*)&sQr[d * 68 + ty * 4];
            float4 qi = *(const float4*)&sQi[d * 68 + ty * 4];
            ulonglong2 kr = *(const ulonglong2*)&sKr[d * 68 + tx * 4];
            ulonglong2 ki = *(const ulonglong2*)&sKi[d * 68 + tx * 4];
#pragma unroll
            for (int i = 0; i < 4; i++) {
                float qrv = ((float*)&qr)[i], qiv = ((float*)&qi)[i];
                u64 pr  = pk2(qrv,  qrv);
                u64 pi_ = pk2(qiv,  qiv);
                u64 pnr = pk2(-qrv, -qrv);
                fma2(sre[i][0], pr,  kr.x); fma2(sre[i][0], pi_, ki.x);
                fma2(sre[i][1], pr,  kr.y); fma2(sre[i][1], pi_, ki.y);
                fma2(sim[i][0], pi_, kr.x); fma2(sim[i][0], pnr, ki.x);
                fma2(sim[i][1], pi_, kr.y); fma2(sim[i][1], pnr, ki.y);
            }
        }
        __syncthreads();   // K reads done; safe to overwrite with P

#pragma unroll
        for (int i = 0; i < 4; i++) {
#pragma unroll
            for (int j = 0; j < 2; j++) {
                float2 re = up2(sre[i][j]), im = up2(sim[i][j]);
                float2 p;
                p.x = __expf(0.125f * __fsqrt_rn(re.x * re.x + im.x * im.x));
                p.y = __expf(0.125f * __fsqrt_rn(re.y * re.y + im.y * im.y));
                lsum[i] += p.x + p.y;
                *(float2*)&sP[(ty * 4 + i) * 68 + tx * 4 + j * 2] = p;
            }
        }
        __syncthreads();

#pragma unroll 8
        for (int kk = 0; kk < 64; kk++) {
            ulonglong2 vr = *(const ulonglong2*)&sVr[kk * 68 + tx * 4];
            ulonglong2 vi = *(const ulonglong2*)&sVi[kk * 68 + tx * 4];
#pragma unroll
            for (int i = 0; i < 4; i++) {
                float pv = sP[(ty * 4 + i) * 68 + kk];
                u64 pp = pk2(pv, pv);
                fma2(ore[i][0], pp, vr.x); fma2(ore[i][1], pp, vr.y);
                fma2(oim[i][0], pp, vi.x); fma2(oim[i][1], pp, vi.y);
            }
        }
    }

    // Reduce row sums across the 16 threads sharing each query row
#pragma unroll
    for (int i = 0; i < 4; i++) {
        float v = lsum[i];
        v += __shfl_xor_sync(0xffffffffu, v, 8);
        v += __shfl_xor_sync(0xffffffffu, v, 4);
        v += __shfl_xor_sync(0xffffffffu, v, 2);
        v += __shfl_xor_sync(0xffffffffu, v, 1);
        lsum[i] = v;
    }

    const int b = bh >> 3, h = bh & 7;
#pragma unroll
    for (int i = 0; i < 4; i++) {
        float inv = __frcp_rn(lsum[i]);
        float2 r0 = up2(ore[i][0]), r1 = up2(ore[i][1]);
        float2 i0 = up2(oim[i][0]), i1 = up2(oim[i][1]);
        size_t idx = ((size_t)(b * NTOK + q0 + ty * 4 + i)) * NDIM + h * 64 + tx * 4;
        *(float4*)(Or_ + idx) = make_float4(r0.x * inv, r0.y * inv, r1.x * inv, r1.y * inv);
        *(float4*)(Oi_ + idx) = make_float4(i0.x * inv, i0.y * inv, i1.x * inv, i1.y * inv);
    }
}

#define ATTN_SMEM (6 * 64 * 68 * 4)

extern "C" void kernel_launch(void* const* d_in, const int* in_sizes, int n_in,
                              void* d_out, int out_size)
{
    const float* Qr  = (const float*)d_in[0];
    const float* Qi  = (const float*)d_in[1];
    const float* Kr  = (const float*)d_in[2];
    const float* Ki  = (const float*)d_in[3];
    const float* Vr  = (const float*)d_in[4];
    const float* Vi  = (const float*)d_in[5];
    const float* wqr = (const float*)d_in[6];
    const float* wqi = (const float*)d_in[7];
    const float* wkr = (const float*)d_in[8];
    const float* wki = (const float*)d_in[9];
    const float* wvr = (const float*)d_in[10];
    const float* wvi = (const float*)d_in[11];
    const float* wor = (const float*)d_in[12];
    const float* woi = (const float*)d_in[13];

    float *qr, *qi, *kr, *ki, *vr, *vi, *orr, *oii;
    cudaGetSymbolAddress((void**)&qr,  g_qr);
    cudaGetSymbolAddress((void**)&qi,  g_qi);
    cudaGetSymbolAddress((void**)&kr,  g_kr);
    cudaGetSymbolAddress((void**)&ki,  g_ki);
    cudaGetSymbolAddress((void**)&vr,  g_vr);
    cudaGetSymbolAddress((void**)&vi,  g_vi);
    cudaGetSymbolAddress((void**)&orr, g_or);
    cudaGetSymbolAddress((void**)&oii, g_oi);

    cudaFuncSetAttribute(attn_kernel,
                         cudaFuncAttributeMaxDynamicSharedMemorySize, ATTN_SMEM);

    dim3 gProj(NDIM / 64, 4096 / 64), blk(256);
    cgemm_nt<0><<<gProj, blk>>>(Qr, Qi, wqr, wqi, qr, qi);
    cgemm_nt<0><<<gProj, blk>>>(Kr, Ki, wkr, wki, kr, ki);
    cgemm_nt<0><<<gProj, blk>>>(Vr, Vi, wvr, wvi, vr, vi);

    attn_kernel<<<dim3(NTOK / 64, 16), blk, ATTN_SMEM>>>(qr, qi, kr, ki, vr, vi, orr, oii);

    cgemm_nt<1><<<gProj, blk>>>(orr, oii, wor, woi, (float*)d_out, nullptr);
}

// round 4
// speedup vs baseline: 1.0008x; 1.0008x over previous
#include <cuda_runtime.h>

// ---------------------------------------------------------------------------
// Complex MHA, fp32 with packed f32x2 FMA inner loops.
// Stage 1: complex input projections (Q,K,V), head-split layout (B,H,N,64)
// Stage 2: fused attention per (b,h): scores (conj), exp(|s|/8), PV, no max
// Stage 3: complex output projection, interleaved (re,im) output
// ---------------------------------------------------------------------------

#define H_HEADS 8
#define NTOK    2048
#define KDIM    512
#define NDIM    512

typedef unsigned long long u64;

__device__ __forceinline__ u64 pk2(float x, float y) {
    u64 r; asm("mov.b64 %0,{%1,%2};" : "=l"(r) : "f"(x), "f"(y)); return r;
}
__device__ __forceinline__ void fma2(u64 &d, u64 a, u64 b) {
    asm("fma.rn.f32x2 %0,%1,%2,%0;" : "+l"(d) : "l"(a), "l"(b));
}
__device__ __forceinline__ float2 up2(u64 v) {
    float2 r; asm("mov.b64 {%0,%1},%2;" : "=f"(r.x), "=f"(r.y) : "l"(v)); return r;
}

// Scratch: projected Q/K/V in (B*H, N, 64) layout; attention out in (B*N, 512)
__device__ float g_qr[16 * 2048 * 64];
__device__ float g_qi[16 * 2048 * 64];
__device__ float g_kr[16 * 2048 * 64];
__device__ float g_ki[16 * 2048 * 64];
__device__ float g_vr[16 * 2048 * 64];
__device__ float g_vi[16 * 2048 * 64];
__device__ float g_or[4096 * 512];
__device__ float g_oi[4096 * 512];

// ---------------------------------------------------------------------------
// Fused complex NT GEMM:  Y = (Ar + iAi) @ (Br + iBi)^T   (B stored (out,in))
//   yr = Ar Br^T - Ai Bi^T ;  yi = Ar Bi^T + Ai Br^T
// MODE 0: write head-split (b, h, n, d) into Or_/Oi_
// MODE 1: write interleaved (yr, yi) pairs into Or_ (final output)
// M = gridDim.y*64 (=4096), N = 512, K = 512
// ---------------------------------------------------------------------------
template<int MODE>
__global__ void __launch_bounds__(256, 2) cgemm_nt(
    const float* __restrict__ Ar, const float* __restrict__ Ai,
    const float* __restrict__ Br, const float* __restrict__ Bi,
    float* __restrict__ Or_, float* __restrict__ Oi_)
{
    __shared__ float sAr[16][68], sAi[16][68], sBr[16][68], sBi[16][68];

    const int tid = threadIdx.x;
    const int tx = tid & 15, ty = tid >> 4;
    const int row = tid >> 2, kq = tid & 3;
    const int mBase = blockIdx.y * 64, nBase = blockIdx.x * 64;

    u64 cre[4][2], cim[4][2];
#pragma unroll
    for (int i = 0; i < 4; i++) {
#pragma unroll
        for (int j = 0; j < 2; j++) { cre[i][j] = 0ull; cim[i][j] = 0ull; }
    }

    const int aoff = (mBase + row) * KDIM + kq * 4;
    const int boff = (nBase + row) * KDIM + kq * 4;

    for (int kc = 0; kc < KDIM; kc += 16) {
        float4 a_r = *(const float4*)(Ar + aoff + kc);
        float4 a_i = *(const float4*)(Ai + aoff + kc);
        float4 b_r = *(const float4*)(Br + boff + kc);
        float4 b_i = *(const float4*)(Bi + boff + kc);
#pragma unroll
        for (int j = 0; j < 4; j++) {
            sAr[kq * 4 + j][row] = ((float*)&a_r)[j];
            sAi[kq * 4 + j][row] = ((float*)&a_i)[j];
            sBr[kq * 4 + j][row] = ((float*)&b_r)[j];
            sBi[kq * 4 + j][row] = ((float*)&b_i)[j];
        }
        __syncthreads();
#pragma unroll
        for (int k = 0; k < 16; k++) {
            float4 ar = *(const float4*)&sAr[k][ty * 4];
            float4 ai = *(const float4*)&sAi[k][ty * 4];
            ulonglong2 br = *(const ulonglong2*)&sBr[k][tx * 4];
            ulonglong2 bi = *(const ulonglong2*)&sBi[k][tx * 4];
#pragma unroll
            for (int i = 0; i < 4; i++) {
                float arv = ((float*)&ar)[i], aiv = ((float*)&ai)[i];
                u64 par  = pk2(arv,  arv);
                u64 pai  = pk2(aiv,  aiv);
                u64 pnai = pk2(-aiv, -aiv);
                fma2(cre[i][0], par,  br.x); fma2(cre[i][0], pnai, bi.x);
                fma2(cre[i][1], par,  br.y); fma2(cre[i][1], pnai, bi.y);
                fma2(cim[i][0], par,  bi.x); fma2(cim[i][0], pai,  br.x);
                fma2(cim[i][1], par,  bi.y); fma2(cim[i][1], pai,  br.y);
            }
        }
        __syncthreads();
    }

#pragma unroll
    for (int i = 0; i < 4; i++) {
        const int m = mBase + ty * 4 + i;
        float2 r0 = up2(cre[i][0]), r1 = up2(cre[i][1]);
        float2 i0 = up2(cim[i][0]), i1 = up2(cim[i][1]);
        if (MODE == 0) {
            const int b = m >> 11, n = m & 2047;
            const int h = nBase >> 6;          // whole 64-col block is one head
            const int d0 = tx * 4;
            size_t idx = ((size_t)((b * H_HEADS + h) * NTOK + n)) * 64 + d0;
            *(float4*)(Or_ + idx) = make_float4(r0.x, r0.y, r1.x, r1.y);
            *(float4*)(Oi_ + idx) = make_float4(i0.x, i0.y, i1.x, i1.y);
        } else {
            const int o0 = nBase + tx * 4;
            size_t base = ((size_t)m * NDIM + o0) * 2;
            *(float4*)(Or_ + base)     = make_float4(r0.x, i0.x, r0.y, i0.y);
            *(float4*)(Or_ + base + 4) = make_float4(r1.x, i1.x, r1.y, i1.y);
        }
    }
}

// ---------------------------------------------------------------------------
// Fused complex attention. Grid: (NQ/64, B*H). Block: 256 threads.
//   s_re = qr kr + qi ki ; s_im = qi kr - qr ki   (Q @ conj(K)^T)
//   p = exp(|s| / 8), no running max (scores are small by construction)
//   o = (sum p V) / (sum p)
// Output written directly in (B, N, H*64) concat layout.
// ---------------------------------------------------------------------------
__global__ void __launch_bounds__(256, 1) attn_kernel(
    const float* __restrict__ Qr, const float* __restrict__ Qi,
    const float* __restrict__ Kr, const float* __restrict__ Ki,
    const float* __restrict__ Vr, const float* __restrict__ Vi,
    float* __restrict__ Or_, float* __restrict__ Oi_)
{
    extern __shared__ float smemf[];
    float* sQr = smemf;
    float* sQi = sQr + 64 * 68;
    float* sKr = sQi + 64 * 68;
    float* sKi = sKr + 64 * 68;
    float* sVr = sKi + 64 * 68;
    float* sVi = sVr + 64 * 68;
    float* sP  = sKr;   // alias: P overwrites K after scores are consumed

    const int tid = threadIdx.x;
    const int tx = tid & 15, ty = tid >> 4;
    const int lr = tid >> 4;   // 0..15 : row within a 16-row chunk
    const int lc = tid & 15;   // 0..15 : which float4 of the 64-wide row
    const int bh = blockIdx.y;
    const int q0 = blockIdx.x * 64;

    const float* Qrb = Qr + ((size_t)bh * NTOK + q0) * 64;
    const float* Qib = Qi + ((size_t)bh * NTOK + q0) * 64;
    const float* Krb = Kr + (size_t)bh * NTOK * 64;
    const float* Kib = Ki + (size_t)bh * NTOK * 64;
    const float* Vrb = Vr + (size_t)bh * NTOK * 64;
    const float* Vib = Vi + (size_t)bh * NTOK * 64;

    // Load full 64x64 Q tile, transposed to [d][q]
#pragma unroll
    for (int c = 0; c < 4; c++) {
        const int r = c * 16 + lr;
        float4 a = *(const float4*)(Qrb + r * 64 + lc * 4);
        float4 b = *(const float4*)(Qib + r * 64 + lc * 4);
#pragma unroll
        for (int j = 0; j < 4; j++) {
            sQr[(lc * 4 + j) * 68 + r] = ((float*)&a)[j];
            sQi[(lc * 4 + j) * 68 + r] = ((float*)&b)[j];
        }
    }

    u64 ore[4][2], oim[4][2];
    float lsum[4];
#pragma unroll
    for (int i = 0; i < 4; i++) {
        lsum[i] = 0.f;
#pragma unroll
        for (int j = 0; j < 2; j++) { ore[i][j] = 0ull; oim[i][j] = 0ull; }
    }

    for (int t = 0; t < NTOK / 64; t++) {
        __syncthreads();   // prev PV readers done (and Q loaded on t=0)
        // Load full 64x64 K (transposed [d][k]) and V (row-major [k][d]) tiles
#pragma unroll
        for (int c = 0; c < 4; c++) {
            const int r = c * 16 + lr;
            const int goff = (t * 64 + r) * 64 + lc * 4;
            float4 kr4 = *(const float4*)(Krb + goff);
            float4 ki4 = *(const float4*)(Kib + goff);
            float4 vr4 = *(const float4*)(Vrb + goff);
            float4 vi4 = *(const float4*)(Vib + goff);
#pragma unroll
            for (int j = 0; j < 4; j++) {
                sKr[(lc * 4 + j) * 68 + r] = ((float*)&kr4)[j];
                sKi[(lc * 4 + j) * 68 + r] = ((float*)&ki4)[j];
            }
            *(float4*)&sVr[r * 68 + lc * 4] = vr4;
            *(float4*)&sVi[r * 68 + lc * 4] = vi4;
        }
        __syncthreads();

        u64 sre[4][2], sim[4][2];
#pragma unroll
        for (int i = 0; i < 4; i++) {
#pragma unroll
            for (int j = 0; j < 2; j++) { sre[i][j] = 0ull; sim[i][j] = 0ull; }
        }

#pragma unroll 8
        for (int d = 0; d < 64; d++) {
            float4 qr = *(const float4*)&sQr[d * 68 + ty * 4];
            float4 qi = *(const float4*)&sQi[d * 68 + ty * 4];
            ulonglong2 kr = *(const ulonglong2*)&sKr[d * 68 + tx * 4];
            ulonglong2 ki = *(const ulonglong2*)&sKi[d * 68 + tx * 4];
#pragma unroll
            for (int i = 0; i < 4; i++) {
                float qrv = ((float*)&qr)[i], qiv = ((float*)&qi)[i];
                u64 pr  = pk2(qrv,  qrv);
                u64 pi_ = pk2(qiv,  qiv);
                u64 pnr = pk2(-qrv, -qrv);
                fma2(sre[i][0], pr,  kr.x); fma2(sre[i][0], pi_, ki.x);
                fma2(sre[i][1], pr,  kr.y); fma2(sre[i][1], pi_, ki.y);
                fma2(sim[i][0], pi_, kr.x); fma2(sim[i][0], pnr, ki.x);
                fma2(sim[i][1], pi_, kr.y); fma2(sim[i][1], pnr, ki.y);
            }
        }
        __syncthreads();   // K reads done; safe to overwrite with P

#pragma unroll
        for (int i = 0; i < 4; i++) {
#pragma unroll
            for (int j = 0; j < 2; j++) {
                float2 re = up2(sre[i][j]), im = up2(sim[i][j]);
                float2 p;
                p.x = __expf(0.125f * __fsqrt_rn(re.x * re.x + im.x * im.x));
                p.y = __expf(0.125f * __fsqrt_rn(re.y * re.y + im.y * im.y));
                lsum[i] += p.x + p.y;
                *(float2*)&sP[(ty * 4 + i) * 68 + tx * 4 + j * 2] = p;
            }
        }
        __syncthreads();

#pragma unroll 8
        for (int kk = 0; kk < 64; kk++) {
            ulonglong2 vr = *(const ulonglong2*)&sVr[kk * 68 + tx * 4];
            ulonglong2 vi = *(const ulonglong2*)&sVi[kk * 68 + tx * 4];
#pragma unroll
            for (int i = 0; i < 4; i++) {
                float pv = sP[(ty * 4 + i) * 68 + kk];
                u64 pp = pk2(pv, pv);
                fma2(ore[i][0], pp, vr.x); fma2(ore[i][1], pp, vr.y);
                fma2(oim[i][0], pp, vi.x); fma2(oim[i][1], pp, vi.y);
            }
        }
    }

    // Reduce row sums across the 16 threads sharing each query row
#pragma unroll
    for (int i = 0; i < 4; i++) {
        float v = lsum[i];
        v += __shfl_xor_sync(0xffffffffu, v, 8);
        v += __shfl_xor_sync(0xffffffffu, v, 4);
        v += __shfl_xor_sync(0xffffffffu, v, 2);
        v += __shfl_xor_sync(0xffffffffu, v, 1);
        lsum[i] = v;
    }

    const int b = bh >> 3, h = bh & 7;
#pragma unroll
    for (int i = 0; i < 4; i++) {
        float inv = __frcp_rn(lsum[i]);
        float2 r0 = up2(ore[i][0]), r1 = up2(ore[i][1]);
        float2 i0 = up2(oim[i][0]), i1 = up2(oim[i][1]);
        size_t idx = ((size_t)(b * NTOK + q0 + ty * 4 + i)) * NDIM + h * 64 + tx * 4;
        *(float4*)(Or_ + idx) = make_float4(r0.x * inv, r0.y * inv, r1.x * inv, r1.y * inv);
        *(float4*)(Oi_ + idx) = make_float4(i0.x * inv, i0.y * inv, i1.x * inv, i1.y * inv);
    }
}

#define ATTN_SMEM (6 * 64 * 68 * 4)

extern "C" void kernel_launch(void* const* d_in, const int* in_sizes, int n_in,
                              void* d_out, int out_size)
{
    const float* Qr  = (const float*)d_in[0];
    const float* Qi  = (const float*)d_in[1];
    const float* Kr  = (const float*)d_in[2];
    const float* Ki  = (const float*)d_in[3];
    const float* Vr  = (const float*)d_in[4];
    const float* Vi  = (const float*)d_in[5];
    const float* wqr = (const float*)d_in[6];
    const float* wqi = (const float*)d_in[7];
    const float* wkr = (const float*)d_in[8];
    const float* wki = (const float*)d_in[9];
    const float* wvr = (const float*)d_in[10];
    const float* wvi = (const float*)d_in[11];
    const float* wor = (const float*)d_in[12];
    const float* woi = (const float*)d_in[13];

    float *qr, *qi, *kr, *ki, *vr, *vi, *orr, *oii;
    cudaGetSymbolAddress((void**)&qr,  g_qr);
    cudaGetSymbolAddress((void**)&qi,  g_qi);
    cudaGetSymbolAddress((void**)&kr,  g_kr);
    cudaGetSymbolAddress((void**)&ki,  g_ki);
    cudaGetSymbolAddress((void**)&vr,  g_vr);
    cudaGetSymbolAddress((void**)&vi,  g_vi);
    cudaGetSymbolAddress((void**)&orr, g_or);
    cudaGetSymbolAddress((void**)&oii, g_oi);

    cudaFuncSetAttribute(attn_kernel,
                         cudaFuncAttributeMaxDynamicSharedMemorySize, ATTN_SMEM);

    dim3 gProj(NDIM / 64, 4096 / 64), blk(256);
    cgemm_nt<0><<<gProj, blk>>>(Qr, Qi, wqr, wqi, qr, qi);
    cgemm_nt<0><<<gProj, blk>>>(Kr, Ki, wkr, wki, kr, ki);
    cgemm_nt<0><<<gProj, blk>>>(Vr, Vi, wvr, wvi, vr, vi);

    attn_kernel<<<dim3(NTOK / 64, 16), blk, ATTN_SMEM>>>(qr, qi, kr, ki, vr, vi, orr, oii);

    cgemm_nt<1><<<gProj, blk>>>(orr, oii, wor, woi, (float*)d_out, nullptr);
}

// round 6
// speedup vs baseline: 1.9499x; 1.9484x over previous
#include <cuda_runtime.h>
#include <cuda_bf16.h>
#include <stdint.h>

// ============================================================================
// Complex MHA on tensor cores (mma.sync m16n8k16 bf16, fp32 accum).
// All fp32 operands split x = hi(bf16) + lo(bf16); products use 3 passes
// (hh + hl + lh)  ->  ~2^-17 relative product error.
// conv -> cgemm<0> x3 (complex projections) -> attn (fused) -> cgemm<1>
// ============================================================================

typedef __nv_bfloat16  bf;
typedef __nv_bfloat162 bf2;
typedef uint32_t u32;

#define NTOK 2048
#define HH   8

// ------------------------------ scratch -------------------------------------
__device__ __align__(16) bf g_in [12][4096 * 512];  // inputs  r/i x hi/lo
__device__ __align__(16) bf g_w  [16][512 * 512];   // weights x hi/lo
__device__ __align__(16) bf g_qkv[12][16 * 2048 * 64]; // q,k,v (r/i x h/l), (b,h,n,d)
__device__ __align__(16) bf g_ao [4][4096 * 512];   // attn out r/i x hi/lo

// ------------------------------ helpers -------------------------------------
__device__ __forceinline__ void ldsm4(u32* r, const bf* p) {
    u32 a = (u32)__cvta_generic_to_shared(p);
    asm volatile("ldmatrix.sync.aligned.m8n8.x4.shared.b16 {%0,%1,%2,%3},[%4];"
                 : "=r"(r[0]), "=r"(r[1]), "=r"(r[2]), "=r"(r[3]) : "r"(a));
}
__device__ __forceinline__ void ldsm4t(u32* r, const bf* p) {
    u32 a = (u32)__cvta_generic_to_shared(p);
    asm volatile("ldmatrix.sync.aligned.m8n8.x4.trans.shared.b16 {%0,%1,%2,%3},[%4];"
                 : "=r"(r[0]), "=r"(r[1]), "=r"(r[2]), "=r"(r[3]) : "r"(a));
}
__device__ __forceinline__ void mma_(float* c, const u32* a, u32 b0, u32 b1) {
    asm volatile(
        "mma.sync.aligned.m16n8k16.row.col.f32.bf16.bf16.f32 "
        "{%0,%1,%2,%3},{%4,%5,%6,%7},{%8,%9},{%0,%1,%2,%3};"
        : "+f"(c[0]), "+f"(c[1]), "+f"(c[2]), "+f"(c[3])
        : "r"(a[0]), "r"(a[1]), "r"(a[2]), "r"(a[3]), "r"(b0), "r"(b1));
}
// non-trans ldsm pointer: rows = (lane&15), col block = (lane>>4)*8
__device__ __forceinline__ const bf* aptr(const bf* b_, int r0, int c0, int st, int ln) {
    return b_ + (r0 + (ln & 15)) * st + c0 + ((ln >> 4) << 3);
}
// trans ldsm pointer (for B from row-major (k,n)): k = (ln&7)+((ln>>3)&1)*8
__device__ __forceinline__ const bf* tptr(const bf* b_, int r0, int c0, int st, int ln) {
    return b_ + (r0 + (ln & 7) + ((ln >> 3) & 1) * 8) * st + c0 + ((ln >> 4) & 1) * 8;
}
__device__ __forceinline__ void split2(float x0, float x1, u32& hi, u32& lo) {
    bf h0 = __float2bfloat16(x0), h1 = __float2bfloat16(x1);
    bf l0 = __float2bfloat16(x0 - __bfloat162float(h0));
    bf l1 = __float2bfloat16(x1 - __bfloat162float(h1));
    bf2 h; h.x = h0; h.y = h1; bf2 l; l.x = l0; l.y = l1;
    hi = *(u32*)&h; lo = *(u32*)&l;
}

// ------------------------ fp32 -> bf16 hi/lo split --------------------------
__global__ void conv_split(const float* __restrict__ s, bf* __restrict__ hi,
                           bf* __restrict__ lo, int n, float scale) {
    int i = (blockIdx.x * 256 + threadIdx.x) * 4;
    if (i >= n) return;
    float4 v = *(const float4*)(s + i);
    v.x *= scale; v.y *= scale; v.z *= scale; v.w *= scale;
    u32 h0, l0, h1, l1;
    split2(v.x, v.y, h0, l0);
    split2(v.z, v.w, h1, l1);
    *(u32*)(hi + i) = h0; *(u32*)(hi + i + 2) = h1;
    *(u32*)(lo + i) = l0; *(u32*)(lo + i + 2) = l1;
}

// ---------------------------------------------------------------------------
// Complex NT GEMM (M=4096, N=512, K=512): Y = A @ W^T, hi/lo 3-pass bf16 mma.
// Block tile 128x64 (8 warps 4x2, warp 32x32). MODE0: head-split bf16 hi/lo
// outputs.  MODE1: fp32 interleaved (re,im) output.
// smem: A 4x[128x40], B 4x[64x40], k-chunk 32.
// ---------------------------------------------------------------------------
#define ASZ (128 * 40)
#define BSZ (64 * 40)
#define GEMM_SMEM ((4 * ASZ + 4 * BSZ) * 2)

template<int MODE>
__global__ void __launch_bounds__(256) cgemm(
    const bf* __restrict__ A0, const bf* __restrict__ A1,
    const bf* __restrict__ A2, const bf* __restrict__ A3,
    const bf* __restrict__ B0, const bf* __restrict__ B1,
    const bf* __restrict__ B2, const bf* __restrict__ B3,
    bf* __restrict__ C0, bf* __restrict__ C1,
    bf* __restrict__ C2, bf* __restrict__ C3, float* __restrict__ Co)
{
    extern __shared__ bf sm[];
    bf* sA = sm;                // 4 tensors x 128x40
    bf* sB = sm + 4 * ASZ;      // 4 tensors x 64x40

    const int tid = threadIdx.x, lane = tid & 31, wid = tid >> 5;
    const int wm = wid >> 1, wn = wid & 1;
    const int mBase = blockIdx.y * 128, nBase = blockIdx.x * 64;

    const bf* Ap[4] = {A0, A1, A2, A3};
    const bf* Bp[4] = {B0, B1, B2, B3};

    float cre[2][4][4], cim[2][4][4];
#pragma unroll
    for (int a = 0; a < 2; a++)
#pragma unroll
        for (int b = 0; b < 4; b++)
#pragma unroll
            for (int c = 0; c < 4; c++) { cre[a][b][c] = 0.f; cim[a][b][c] = 0.f; }

    for (int kc = 0; kc < 16; kc++) {
        __syncthreads();
#pragma unroll
        for (int t = 0; t < 4; t++) {
#pragma unroll
            for (int i = 0; i < 2; i++) {
                int idx = i * 256 + tid, row = idx >> 2, col = (idx & 3) * 8;
                *(float4*)(sA + t * ASZ + row * 40 + col) =
                    *(const float4*)(Ap[t] + (size_t)(mBase + row) * 512 + kc * 32 + col);
            }
            {
                int row = tid >> 2, col = (tid & 3) * 8;
                *(float4*)(sB + t * BSZ + row * 40 + col) =
                    *(const float4*)(Bp[t] + (size_t)(nBase + row) * 512 + kc * 32 + col);
            }
        }
        __syncthreads();

#pragma unroll
        for (int ks = 0; ks < 2; ks++) {
            u32 af[4][2][4];
#pragma unroll
            for (int t = 0; t < 4; t++)
#pragma unroll
                for (int mt = 0; mt < 2; mt++)
                    ldsm4(af[t][mt], aptr(sA + t * ASZ, wm * 32 + mt * 16, ks * 16, 40, lane));
            u32 bg[4][8];
#pragma unroll
            for (int t = 0; t < 4; t++) {
                ldsm4(bg[t],     aptr(sB + t * BSZ, wn * 32,      ks * 16, 40, lane));
                ldsm4(bg[t] + 4, aptr(sB + t * BSZ, wn * 32 + 16, ks * 16, 40, lane));
            }
#pragma unroll
            for (int mt = 0; mt < 2; mt++) {
                u32 n2[4], n3[4];   // negated Ai hi/lo (for yr -= Ai*Bi)
#pragma unroll
                for (int r = 0; r < 4; r++) {
                    n2[r] = af[2][mt][r] ^ 0x80008000u;
                    n3[r] = af[3][mt][r] ^ 0x80008000u;
                }
#pragma unroll
                for (int nt = 0; nt < 4; nt++) {
                    int i0 = (nt >> 1) * 4 + (nt & 1), i1 = i0 + 2;
                    float* cr = cre[mt][nt]; float* ci = cim[mt][nt];
                    mma_(cr, af[0][mt], bg[0][i0], bg[0][i1]);  // rh*rh
                    mma_(cr, af[0][mt], bg[1][i0], bg[1][i1]);  // rh*rl
                    mma_(cr, af[1][mt], bg[0][i0], bg[0][i1]);  // rl*rh
                    mma_(cr, n2,        bg[2][i0], bg[2][i1]);  // -ih*ih
                    mma_(cr, n2,        bg[3][i0], bg[3][i1]);  // -ih*il
                    mma_(cr, n3,        bg[2][i0], bg[2][i1]);  // -il*ih
                    mma_(ci, af[0][mt], bg[2][i0], bg[2][i1]);  // rh*ih
                    mma_(ci, af[0][mt], bg[3][i0], bg[3][i1]);  // rh*il
                    mma_(ci, af[1][mt], bg[2][i0], bg[2][i1]);  // rl*ih
                    mma_(ci, af[2][mt], bg[0][i0], bg[0][i1]);  // ih*rh
                    mma_(ci, af[2][mt], bg[1][i0], bg[1][i1]);  // ih*rl
                    mma_(ci, af[3][mt], bg[0][i0], bg[0][i1]);  // il*rh
                }
            }
        }
    }

    const int g = lane >> 2, t2 = (lane & 3) * 2;
#pragma unroll
    for (int mt = 0; mt < 2; mt++)
#pragma unroll
        for (int nt = 0; nt < 4; nt++) {
            int c0 = wn * 32 + nt * 8 + t2;
#pragma unroll
            for (int hf = 0; hf < 2; hf++) {
                int m = mBase + wm * 32 + mt * 16 + g + hf * 8;
                float yr0 = cre[mt][nt][hf * 2], yr1 = cre[mt][nt][hf * 2 + 1];
                float yi0 = cim[mt][nt][hf * 2], yi1 = cim[mt][nt][hf * 2 + 1];
                if (MODE == 0) {
                    int b = m >> 11, ntok = m & 2047, h = blockIdx.x;
                    size_t base = ((size_t)((b * HH + h) * NTOK + ntok)) * 64 + c0;
                    u32 rh, rl, ih, il;
                    split2(yr0, yr1, rh, rl);
                    split2(yi0, yi1, ih, il);
                    *(u32*)(C0 + base) = rh; *(u32*)(C1 + base) = rl;
                    *(u32*)(C2 + base) = ih; *(u32*)(C3 + base) = il;
                } else {
                    size_t base = ((size_t)m * 512 + nBase + c0) * 2;
                    *(float4*)(Co + base) = make_float4(yr0, yi0, yr1, yi1);
                }
            }
        }
}

// ---------------------------------------------------------------------------
// Fused complex attention. Grid (16 q-blocks, 16 bh). Block 256 = 8 warps,
// warp owns 16 q rows x full 64-k tile. P stays in registers (accum-frag ==
// A-frag layout). smem: Q 4x[128x72], K 4x[64x72], V 4x[64x72].
// ---------------------------------------------------------------------------
#define QS (128 * 72)
#define KS (64 * 72)
#define ATTN_SMEM ((4 * QS + 8 * KS) * 2)

__global__ void __launch_bounds__(256) attn(
    const bf* __restrict__ q0p, const bf* __restrict__ q1p,
    const bf* __restrict__ q2p, const bf* __restrict__ q3p,
    const bf* __restrict__ k0p, const bf* __restrict__ k1p,
    const bf* __restrict__ k2p, const bf* __restrict__ k3p,
    const bf* __restrict__ v0p, const bf* __restrict__ v1p,
    const bf* __restrict__ v2p, const bf* __restrict__ v3p,
    bf* __restrict__ aorh, bf* __restrict__ aorl,
    bf* __restrict__ aoih, bf* __restrict__ aoil)
{
    extern __shared__ bf sm[];
    bf* sQ = sm;
    bf* sK = sm + 4 * QS;
    bf* sV = sK + 4 * KS;

    const int tid = threadIdx.x, lane = tid & 31, wid = tid >> 5;
    const int bh = blockIdx.y, q0 = blockIdx.x * 128;
    const bf* qp[4] = {q0p, q1p, q2p, q3p};
    const bf* kp[4] = {k0p, k1p, k2p, k3p};
    const bf* vp[4] = {v0p, v1p, v2p, v3p};

    // load Q tile once
#pragma unroll
    for (int t = 0; t < 4; t++)
#pragma unroll
        for (int i = 0; i < 4; i++) {
            int idx = i * 256 + tid, row = idx >> 3, col = (idx & 7) * 8;
            *(float4*)(sQ + t * QS + row * 72 + col) =
                *(const float4*)(qp[t] + ((size_t)(bh * NTOK + q0 + row)) * 64 + col);
        }

    float o_r[8][4], o_i[8][4];
#pragma unroll
    for (int a = 0; a < 8; a++)
#pragma unroll
        for (int b = 0; b < 4; b++) { o_r[a][b] = 0.f; o_i[a][b] = 0.f; }
    float ls0 = 0.f, ls1 = 0.f;

    for (int kt = 0; kt < 32; kt++) {
        __syncthreads();
#pragma unroll
        for (int t = 0; t < 4; t++)
#pragma unroll
            for (int i = 0; i < 2; i++) {
                int idx = i * 256 + tid, row = idx >> 3, col = (idx & 7) * 8;
                size_t go = ((size_t)(bh * NTOK + kt * 64 + row)) * 64 + col;
                *(float4*)(sK + t * KS + row * 72 + col) = *(const float4*)(kp[t] + go);
                *(float4*)(sV + t * KS + row * 72 + col) = *(const float4*)(vp[t] + go);
            }
        __syncthreads();

        // ---- scores: S = Q conj(K)^T (hi/lo 3-pass) ----
        float sre[8][4], sim[8][4];
#pragma unroll
        for (int a = 0; a < 8; a++)
#pragma unroll
            for (int b = 0; b < 4; b++) { sre[a][b] = 0.f; sim[a][b] = 0.f; }

#pragma unroll
        for (int dc = 0; dc < 4; dc++) {
            u32 qf[4][4];
#pragma unroll
            for (int t = 0; t < 4; t++)
                ldsm4(qf[t], aptr(sQ + t * QS, wid * 16, dc * 16, 72, lane));
            u32 n0[4], n1[4];   // negated qr hi/lo (for sim -= qr*ki)
#pragma unroll
            for (int r = 0; r < 4; r++) {
                n0[r] = qf[0][r] ^ 0x80008000u;
                n1[r] = qf[1][r] ^ 0x80008000u;
            }
#pragma unroll
            for (int nh = 0; nh < 2; nh++) {
                u32 kf[4][8];
#pragma unroll
                for (int t = 0; t < 4; t++) {
                    ldsm4(kf[t],     aptr(sK + t * KS, nh * 32,      dc * 16, 72, lane));
                    ldsm4(kf[t] + 4, aptr(sK + t * KS, nh * 32 + 16, dc * 16, 72, lane));
                }
#pragma unroll
                for (int n4 = 0; n4 < 4; n4++) {
                    int nt = nh * 4 + n4;
                    int i0 = (n4 >> 1) * 4 + (n4 & 1), i1 = i0 + 2;
                    float* cr = sre[nt]; float* ci = sim[nt];
                    mma_(cr, qf[0], kf[0][i0], kf[0][i1]);  // qrh*krh
                    mma_(cr, qf[0], kf[1][i0], kf[1][i1]);  // qrh*krl
                    mma_(cr, qf[1], kf[0][i0], kf[0][i1]);  // qrl*krh
                    mma_(cr, qf[2], kf[2][i0], kf[2][i1]);  // qih*kih
                    mma_(cr, qf[2], kf[3][i0], kf[3][i1]);  // qih*kil
                    mma_(cr, qf[3], kf[2][i0], kf[2][i1]);  // qil*kih
                    mma_(ci, qf[2], kf[0][i0], kf[0][i1]);  // qih*krh
                    mma_(ci, qf[2], kf[1][i0], kf[1][i1]);  // qih*krl
                    mma_(ci, qf[3], kf[0][i0], kf[0][i1]);  // qil*krh
                    mma_(ci, n0,    kf[2][i0], kf[2][i1]);  // -qrh*kih
                    mma_(ci, n0,    kf[3][i0], kf[3][i1]);  // -qrh*kil
                    mma_(ci, n1,    kf[2][i0], kf[2][i1]);  // -qrl*kih
                }
            }
        }

        // ---- p = exp(|s|), register repack S-accum -> P A-frags ----
        u32 ph[4][4], pl[4][4];
#pragma unroll
        for (int kc = 0; kc < 4; kc++) {
            float pv[2][4];
#pragma unroll
            for (int h2 = 0; h2 < 2; h2++) {
                int nt = kc * 2 + h2;
#pragma unroll
                for (int e = 0; e < 4; e++) {
                    float u = sre[nt][e] * sre[nt][e] + sim[nt][e] * sim[nt][e];
                    pv[h2][e] = __expf(__fsqrt_rn(u));
                }
            }
            ls0 += pv[0][0] + pv[0][1] + pv[1][0] + pv[1][1];
            ls1 += pv[0][2] + pv[0][3] + pv[1][2] + pv[1][3];
            split2(pv[0][0], pv[0][1], ph[kc][0], pl[kc][0]);
            split2(pv[0][2], pv[0][3], ph[kc][1], pl[kc][1]);
            split2(pv[1][0], pv[1][1], ph[kc][2], pl[kc][2]);
            split2(pv[1][2], pv[1][3], ph[kc][3], pl[kc][3]);
        }

        // ---- O += P V (hi/lo 3-pass), V via trans ldmatrix ----
#pragma unroll
        for (int kc = 0; kc < 4; kc++)
#pragma unroll
            for (int dh = 0; dh < 2; dh++) {
                u32 vf[4][8];
#pragma unroll
                for (int t = 0; t < 4; t++) {
                    ldsm4t(vf[t],     tptr(sV + t * KS, kc * 16, dh * 32,      72, lane));
                    ldsm4t(vf[t] + 4, tptr(sV + t * KS, kc * 16, dh * 32 + 16, 72, lane));
                }
#pragma unroll
                for (int dt = 0; dt < 4; dt++) {
                    int od = dh * 4 + dt, j0 = dt * 2, j1 = dt * 2 + 1;
                    mma_(o_r[od], ph[kc], vf[0][j0], vf[0][j1]);  // ph*vrh
                    mma_(o_r[od], ph[kc], vf[1][j0], vf[1][j1]);  // ph*vrl
                    mma_(o_r[od], pl[kc], vf[0][j0], vf[0][j1]);  // pl*vrh
                    mma_(o_i[od], ph[kc], vf[2][j0], vf[2][j1]);  // ph*vih
                    mma_(o_i[od], ph[kc], vf[3][j0], vf[3][j1]);  // ph*vil
                    mma_(o_i[od], pl[kc], vf[2][j0], vf[2][j1]);  // pl*vih
                }
            }
    }

    // ---- normalize + write (b, tok, h*64+d) bf16 hi/lo ----
    ls0 += __shfl_xor_sync(0xffffffffu, ls0, 1);
    ls0 += __shfl_xor_sync(0xffffffffu, ls0, 2);
    ls1 += __shfl_xor_sync(0xffffffffu, ls1, 1);
    ls1 += __shfl_xor_sync(0xffffffffu, ls1, 2);
    float inv0 = 1.0f / ls0, inv1 = 1.0f / ls1;

    const int g = lane >> 2, t2 = (lane & 3) * 2;
    const int b = bh >> 3, h = bh & 7;
    const int r0 = q0 + wid * 16 + g;
#pragma unroll
    for (int od = 0; od < 8; od++) {
        int col = h * 64 + od * 8 + t2;
        size_t a0 = ((size_t)(b * NTOK + r0)) * 512 + col;
        size_t a1 = a0 + (size_t)8 * 512;
        u32 rh, rl, ih, il;
        split2(o_r[od][0] * inv0, o_r[od][1] * inv0, rh, rl);
        split2(o_i[od][0] * inv0, o_i[od][1] * inv0, ih, il);
        *(u32*)(aorh + a0) = rh; *(u32*)(aorl + a0) = rl;
        *(u32*)(aoih + a0) = ih; *(u32*)(aoil + a0) = il;
        split2(o_r[od][2] * inv1, o_r[od][3] * inv1, rh, rl);
        split2(o_i[od][2] * inv1, o_i[od][3] * inv1, ih, il);
        *(u32*)(aorh + a1) = rh; *(u32*)(aorl + a1) = rl;
        *(u32*)(aoih + a1) = ih; *(u32*)(aoil + a1) = il;
    }
}

// ---------------------------------------------------------------------------
extern "C" void kernel_launch(void* const* d_in, const int* in_sizes, int n_in,
                              void* d_out, int out_size)
{
    // Base addresses of the 2-D scratch symbols, then plain pointer math.
    bf *inB, *wB, *qkvB, *aoB;
    cudaGetSymbolAddress((void**)&inB,  g_in);
    cudaGetSymbolAddress((void**)&wB,   g_w);
    cudaGetSymbolAddress((void**)&qkvB, g_qkv);
    cudaGetSymbolAddress((void**)&aoB,  g_ao);

    bf *in_[12], *w_[16], *qkv_[12], *ao_[4];
    for (int t = 0; t < 12; t++) in_[t]  = inB  + (size_t)t * (4096 * 512);
    for (int t = 0; t < 16; t++) w_[t]   = wB   + (size_t)t * (512 * 512);
    for (int t = 0; t < 12; t++) qkv_[t] = qkvB + (size_t)t * (16 * 2048 * 64);
    for (int t = 0; t < 4;  t++) ao_[t]  = aoB  + (size_t)t * (4096 * 512);

    cudaFuncSetAttribute(cgemm<0>, cudaFuncAttributeMaxDynamicSharedMemorySize, GEMM_SMEM);
    cudaFuncSetAttribute(cgemm<1>, cudaFuncAttributeMaxDynamicSharedMemorySize, GEMM_SMEM);
    cudaFuncSetAttribute(attn,     cudaFuncAttributeMaxDynamicSharedMemorySize, ATTN_SMEM);

    const int NIN = 4096 * 512, NW = 512 * 512;
    // inputs: Qr Qi Kr Ki Vr Vi  -> g_in[0..11] (hi,lo pairs)
    for (int t = 0; t < 6; t++)
        conv_split<<<NIN / 1024, 256>>>((const float*)d_in[t], in_[2 * t], in_[2 * t + 1], NIN, 1.0f);
    // weights: wq_r wq_i wk_r wk_i wv_r wv_i wo_r wo_i -> g_w[0..15]
    for (int t = 0; t < 8; t++) {
        float sc = (t < 2) ? 0.125f : 1.0f;   // fold 1/sqrt(64) into wq
        conv_split<<<NW / 1024, 256>>>((const float*)d_in[6 + t], w_[2 * t], w_[2 * t + 1], NW, sc);
    }

    dim3 gg(8, 32), blk(256);
    cgemm<0><<<gg, blk, GEMM_SMEM>>>(in_[0], in_[1], in_[2], in_[3],
                                     w_[0], w_[1], w_[2], w_[3],
                                     qkv_[0], qkv_[1], qkv_[2], qkv_[3], nullptr);
    cgemm<0><<<gg, blk, GEMM_SMEM>>>(in_[4], in_[5], in_[6], in_[7],
                                     w_[4], w_[5], w_[6], w_[7],
                                     qkv_[4], qkv_[5], qkv_[6], qkv_[7], nullptr);
    cgemm<0><<<gg, blk, GEMM_SMEM>>>(in_[8], in_[9], in_[10], in_[11],
                                     w_[8], w_[9], w_[10], w_[11],
                                     qkv_[8], qkv_[9], qkv_[10], qkv_[11], nullptr);

    attn<<<dim3(16, 16), blk, ATTN_SMEM>>>(
        qkv_[0], qkv_[1], qkv_[2], qkv_[3],
        qkv_[4], qkv_[5], qkv_[6], qkv_[7],
        qkv_[8], qkv_[9], qkv_[10], qkv_[11],
        ao_[0], ao_[1], ao_[2], ao_[3]);

    cgemm<1><<<gg, blk, GEMM_SMEM>>>(ao_[0], ao_[1], ao_[2], ao_[3],
                                     w_[12], w_[13], w_[14], w_[15],
                                     nullptr, nullptr, nullptr, nullptr, (float*)d_out);
}

// round 7
// speedup vs baseline: 2.0797x; 1.0666x over previous
#include <cuda_runtime.h>
#include <cuda_bf16.h>
#include <stdint.h>

// ============================================================================
// Complex MHA on tensor cores (mma.sync m16n8k16 bf16, fp32 accum).
// All fp32 operands split x = hi(bf16) + lo(bf16); products use 3 passes
// (hh + hl + lh)  ->  ~2^-17 relative product error.
// R7: cp.async double-buffered pipelines in cgemm + attn; merged conv.
// ============================================================================

typedef __nv_bfloat16  bf;
typedef __nv_bfloat162 bf2;
typedef uint32_t u32;

#define NTOK 2048
#define HH   8
#define NIN  (4096 * 512)
#define NW   (512 * 512)

// ------------------------------ scratch -------------------------------------
__device__ __align__(16) bf g_in [12][NIN];            // inputs  r/i x hi/lo
__device__ __align__(16) bf g_w  [16][NW];             // weights x hi/lo
__device__ __align__(16) bf g_qkv[12][16 * 2048 * 64]; // q,k,v (r/i x h/l)
__device__ __align__(16) bf g_ao [4][4096 * 512];      // attn out r/i x hi/lo

// ------------------------------ helpers -------------------------------------
__device__ __forceinline__ void ldsm4(u32* r, const bf* p) {
    u32 a = (u32)__cvta_generic_to_shared(p);
    asm volatile("ldmatrix.sync.aligned.m8n8.x4.shared.b16 {%0,%1,%2,%3},[%4];"
                 : "=r"(r[0]), "=r"(r[1]), "=r"(r[2]), "=r"(r[3]) : "r"(a));
}
__device__ __forceinline__ void ldsm4t(u32* r, const bf* p) {
    u32 a = (u32)__cvta_generic_to_shared(p);
    asm volatile("ldmatrix.sync.aligned.m8n8.x4.trans.shared.b16 {%0,%1,%2,%3},[%4];"
                 : "=r"(r[0]), "=r"(r[1]), "=r"(r[2]), "=r"(r[3]) : "r"(a));
}
__device__ __forceinline__ void mma_(float* c, const u32* a, u32 b0, u32 b1) {
    asm volatile(
        "mma.sync.aligned.m16n8k16.row.col.f32.bf16.bf16.f32 "
        "{%0,%1,%2,%3},{%4,%5,%6,%7},{%8,%9},{%0,%1,%2,%3};"
        : "+f"(c[0]), "+f"(c[1]), "+f"(c[2]), "+f"(c[3])
        : "r"(a[0]), "r"(a[1]), "r"(a[2]), "r"(a[3]), "r"(b0), "r"(b1));
}
__device__ __forceinline__ void cpa(bf* dst, const bf* src) {
    u32 a = (u32)__cvta_generic_to_shared(dst);
    asm volatile("cp.async.cg.shared.global [%0],[%1],16;" :: "r"(a), "l"(src));
}
#define CP_COMMIT asm volatile("cp.async.commit_group;")
#define CP_WAIT1  asm volatile("cp.async.wait_group 1;")
#define CP_WAIT0  asm volatile("cp.async.wait_group 0;")

// non-trans ldsm pointer: rows = (lane&15), col block = (lane>>4)*8
__device__ __forceinline__ const bf* aptr(const bf* b_, int r0, int c0, int st, int ln) {
    return b_ + (r0 + (ln & 15)) * st + c0 + ((ln >> 4) << 3);
}
// trans ldsm pointer (for B from row-major (k,n)): k = (ln&7)+((ln>>3)&1)*8
__device__ __forceinline__ const bf* tptr(const bf* b_, int r0, int c0, int st, int ln) {
    return b_ + (r0 + (ln & 7) + ((ln >> 3) & 1) * 8) * st + c0 + ((ln >> 4) & 1) * 8;
}
__device__ __forceinline__ void split2(float x0, float x1, u32& hi, u32& lo) {
    bf h0 = __float2bfloat16(x0), h1 = __float2bfloat16(x1);
    bf l0 = __float2bfloat16(x0 - __bfloat162float(h0));
    bf l1 = __float2bfloat16(x1 - __bfloat162float(h1));
    bf2 h; h.x = h0; h.y = h1; bf2 l; l.x = l0; l.y = l1;
    hi = *(u32*)&h; lo = *(u32*)&l;
}

// ------------------- fp32 -> bf16 hi/lo split (merged) ----------------------
__global__ void conv_in(const float* s0, const float* s1, const float* s2,
                        const float* s3, const float* s4, const float* s5,
                        bf* inB) {
    const int t = blockIdx.y;
    const float* s;
    switch (t) {
        case 0: s = s0; break; case 1: s = s1; break; case 2: s = s2; break;
        case 3: s = s3; break; case 4: s = s4; break; default: s = s5; break;
    }
    bf* hi = inB + (size_t)(2 * t) * NIN;
    bf* lo = hi + NIN;
    int i = (blockIdx.x * 256 + threadIdx.x) * 4;
    float4 v = *(const float4*)(s + i);
    u32 h0, l0, h1, l1;
    split2(v.x, v.y, h0, l0);
    split2(v.z, v.w, h1, l1);
    *(u32*)(hi + i) = h0; *(u32*)(hi + i + 2) = h1;
    *(u32*)(lo + i) = l0; *(u32*)(lo + i + 2) = l1;
}

__global__ void conv_w(const float* s0, const float* s1, const float* s2,
                       const float* s3, const float* s4, const float* s5,
                       const float* s6, const float* s7, bf* wB) {
    const int t = blockIdx.y;
    const float* s;
    switch (t) {
        case 0: s = s0; break; case 1: s = s1; break; case 2: s = s2; break;
        case 3: s = s3; break; case 4: s = s4; break; case 5: s = s5; break;
        case 6: s = s6; break; default: s = s7; break;
    }
    const float sc = (t < 2) ? 0.125f : 1.0f;   // fold 1/sqrt(64) into wq
    bf* hi = wB + (size_t)(2 * t) * NW;
    bf* lo = hi + NW;
    int i = (blockIdx.x * 256 + threadIdx.x) * 4;
    float4 v = *(const float4*)(s + i);
    v.x *= sc; v.y *= sc; v.z *= sc; v.w *= sc;
    u32 h0, l0, h1, l1;
    split2(v.x, v.y, h0, l0);
    split2(v.z, v.w, h1, l1);
    *(u32*)(hi + i) = h0; *(u32*)(hi + i + 2) = h1;
    *(u32*)(lo + i) = l0; *(u32*)(lo + i + 2) = l1;
}

// ---------------------------------------------------------------------------
// Complex NT GEMM (M=4096, N=512, K=512), hi/lo 3-pass bf16 mma.
// Block tile 128x64 (8 warps 4x2, warp 32x32), cp.async 2-stage pipeline.
// ---------------------------------------------------------------------------
#define ASZ (128 * 40)
#define BSZ (64 * 40)
#define STG (4 * ASZ + 4 * BSZ)
#define GEMM_SMEM (2 * STG * 2)

template<int MODE>
__global__ void __launch_bounds__(256) cgemm(
    const bf* __restrict__ A0, const bf* __restrict__ A1,
    const bf* __restrict__ A2, const bf* __restrict__ A3,
    const bf* __restrict__ B0, const bf* __restrict__ B1,
    const bf* __restrict__ B2, const bf* __restrict__ B3,
    bf* __restrict__ C0, bf* __restrict__ C1,
    bf* __restrict__ C2, bf* __restrict__ C3, float* __restrict__ Co)
{
    extern __shared__ bf sm[];
    const int tid = threadIdx.x, lane = tid & 31, wid = tid >> 5;
    const int wm = wid >> 1, wn = wid & 1;
    const int mBase = blockIdx.y * 128, nBase = blockIdx.x * 64;

    const bf* Ap[4] = {A0, A1, A2, A3};
    const bf* Bp[4] = {B0, B1, B2, B3};

    float cre[2][4][4], cim[2][4][4];
#pragma unroll
    for (int a = 0; a < 2; a++)
#pragma unroll
        for (int b = 0; b < 4; b++)
#pragma unroll
            for (int c = 0; c < 4; c++) { cre[a][b][c] = 0.f; cim[a][b][c] = 0.f; }

    // stage issue: A 4x[128x32], B 4x[64x32] via cp.async
    auto issue = [&](int kc, int d) {
        bf* sA = sm + d * STG;
        bf* sB = sA + 4 * ASZ;
#pragma unroll
        for (int t = 0; t < 4; t++) {
#pragma unroll
            for (int i = 0; i < 2; i++) {
                int idx = i * 256 + tid, row = idx >> 2, col = (idx & 3) * 8;
                cpa(sA + t * ASZ + row * 40 + col,
                    Ap[t] + (size_t)(mBase + row) * 512 + kc * 32 + col);
            }
            int row = tid >> 2, col = (tid & 3) * 8;
            cpa(sB + t * BSZ + row * 40 + col,
                Bp[t] + (size_t)(nBase + row) * 512 + kc * 32 + col);
        }
    };

    issue(0, 0); CP_COMMIT;

    for (int kc = 0; kc < 16; kc++) {
        if (kc < 15) { issue(kc + 1, (kc + 1) & 1); CP_COMMIT; CP_WAIT1; }
        else         { CP_WAIT0; }
        __syncthreads();

        bf* sA = sm + (kc & 1) * STG;
        bf* sB = sA + 4 * ASZ;

#pragma unroll
        for (int ks = 0; ks < 2; ks++) {
            u32 af[4][2][4];
#pragma unroll
            for (int t = 0; t < 4; t++)
#pragma unroll
                for (int mt = 0; mt < 2; mt++)
                    ldsm4(af[t][mt], aptr(sA + t * ASZ, wm * 32 + mt * 16, ks * 16, 40, lane));
            u32 bg[4][8];
#pragma unroll
            for (int t = 0; t < 4; t++) {
                ldsm4(bg[t],     aptr(sB + t * BSZ, wn * 32,      ks * 16, 40, lane));
                ldsm4(bg[t] + 4, aptr(sB + t * BSZ, wn * 32 + 16, ks * 16, 40, lane));
            }
#pragma unroll
            for (int mt = 0; mt < 2; mt++) {
                u32 n2[4], n3[4];   // negated Ai hi/lo
#pragma unroll
                for (int r = 0; r < 4; r++) {
                    n2[r] = af[2][mt][r] ^ 0x80008000u;
                    n3[r] = af[3][mt][r] ^ 0x80008000u;
                }
#pragma unroll
                for (int nt = 0; nt < 4; nt++) {
                    int i0 = (nt >> 1) * 4 + (nt & 1), i1 = i0 + 2;
                    float* cr = cre[mt][nt]; float* ci = cim[mt][nt];
                    mma_(cr, af[0][mt], bg[0][i0], bg[0][i1]);
                    mma_(cr, af[0][mt], bg[1][i0], bg[1][i1]);
                    mma_(cr, af[1][mt], bg[0][i0], bg[0][i1]);
                    mma_(cr, n2,        bg[2][i0], bg[2][i1]);
                    mma_(cr, n2,        bg[3][i0], bg[3][i1]);
                    mma_(cr, n3,        bg[2][i0], bg[2][i1]);
                    mma_(ci, af[0][mt], bg[2][i0], bg[2][i1]);
                    mma_(ci, af[0][mt], bg[3][i0], bg[3][i1]);
                    mma_(ci, af[1][mt], bg[2][i0], bg[2][i1]);
                    mma_(ci, af[2][mt], bg[0][i0], bg[0][i1]);
                    mma_(ci, af[2][mt], bg[1][i0], bg[1][i1]);
                    mma_(ci, af[3][mt], bg[0][i0], bg[0][i1]);
                }
            }
        }
        __syncthreads();
    }

    const int g = lane >> 2, t2 = (lane & 3) * 2;
#pragma unroll
    for (int mt = 0; mt < 2; mt++)
#pragma unroll
        for (int nt = 0; nt < 4; nt++) {
            int c0 = wn * 32 + nt * 8 + t2;
#pragma unroll
            for (int hf = 0; hf < 2; hf++) {
                int m = mBase + wm * 32 + mt * 16 + g + hf * 8;
                float yr0 = cre[mt][nt][hf * 2], yr1 = cre[mt][nt][hf * 2 + 1];
                float yi0 = cim[mt][nt][hf * 2], yi1 = cim[mt][nt][hf * 2 + 1];
                if (MODE == 0) {
                    int b = m >> 11, ntok = m & 2047, h = blockIdx.x;
                    size_t base = ((size_t)((b * HH + h) * NTOK + ntok)) * 64 + c0;
                    u32 rh, rl, ih, il;
                    split2(yr0, yr1, rh, rl);
                    split2(yi0, yi1, ih, il);
                    *(u32*)(C0 + base) = rh; *(u32*)(C1 + base) = rl;
                    *(u32*)(C2 + base) = ih; *(u32*)(C3 + base) = il;
                } else {
                    size_t base = ((size_t)m * 512 + nBase + c0) * 2;
                    *(float4*)(Co + base) = make_float4(yr0, yi0, yr1, yi1);
                }
            }
        }
}

// ---------------------------------------------------------------------------
// Fused complex attention, cp.async 2-stage K/V pipeline.
// Grid (16 q-blocks, 16 bh). 8 warps; warp = 16 q rows x full 64-k tile.
// ---------------------------------------------------------------------------
#define QS (128 * 72)
#define KS (64 * 72)
#define KVSTG (8 * KS)
#define ATTN_SMEM ((4 * QS + 2 * KVSTG) * 2)

__global__ void __launch_bounds__(256) attn(
    const bf* __restrict__ q0p, const bf* __restrict__ q1p,
    const bf* __restrict__ q2p, const bf* __restrict__ q3p,
    const bf* __restrict__ k0p, const bf* __restrict__ k1p,
    const bf* __restrict__ k2p, const bf* __restrict__ k3p,
    const bf* __restrict__ v0p, const bf* __restrict__ v1p,
    const bf* __restrict__ v2p, const bf* __restrict__ v3p,
    bf* __restrict__ aorh, bf* __restrict__ aorl,
    bf* __restrict__ aoih, bf* __restrict__ aoil)
{
    extern __shared__ bf sm[];
    bf* sQ = sm;

    const int tid = threadIdx.x, lane = tid & 31, wid = tid >> 5;
    const int bh = blockIdx.y, q0 = blockIdx.x * 128;
    const bf* qp[4] = {q0p, q1p, q2p, q3p};
    const bf* kp[4] = {k0p, k1p, k2p, k3p};
    const bf* vp[4] = {v0p, v1p, v2p, v3p};

    auto issue_kv = [&](int kt, int d) {
        bf* sK = sm + 4 * QS + d * KVSTG;
        bf* sV = sK + 4 * KS;
#pragma unroll
        for (int t = 0; t < 4; t++)
#pragma unroll
            for (int i = 0; i < 2; i++) {
                int idx = i * 256 + tid, row = idx >> 3, col = (idx & 7) * 8;
                size_t go = ((size_t)(bh * NTOK + kt * 64 + row)) * 64 + col;
                cpa(sK + t * KS + row * 72 + col, kp[t] + go);
                cpa(sV + t * KS + row * 72 + col, vp[t] + go);
            }
    };

    issue_kv(0, 0); CP_COMMIT;

    // load Q tile once (plain stores; visible after first barrier)
#pragma unroll
    for (int t = 0; t < 4; t++)
#pragma unroll
        for (int i = 0; i < 4; i++) {
            int idx = i * 256 + tid, row = idx >> 3, col = (idx & 7) * 8;
            *(float4*)(sQ + t * QS + row * 72 + col) =
                *(const float4*)(qp[t] + ((size_t)(bh * NTOK + q0 + row)) * 64 + col);
        }

    float o_r[8][4], o_i[8][4];
#pragma unroll
    for (int a = 0; a < 8; a++)
#pragma unroll
        for (int b = 0; b < 4; b++) { o_r[a][b] = 0.f; o_i[a][b] = 0.f; }
    float ls0 = 0.f, ls1 = 0.f;

    for (int kt = 0; kt < 32; kt++) {
        if (kt < 31) { issue_kv(kt + 1, (kt + 1) & 1); CP_COMMIT; CP_WAIT1; }
        else         { CP_WAIT0; }
        __syncthreads();

        bf* sK = sm + 4 * QS + (kt & 1) * KVSTG;
        bf* sV = sK + 4 * KS;

        // ---- scores: S = Q conj(K)^T (hi/lo 3-pass) ----
        float sre[8][4], sim[8][4];
#pragma unroll
        for (int a = 0; a < 8; a++)
#pragma unroll
            for (int b = 0; b < 4; b++) { sre[a][b] = 0.f; sim[a][b] = 0.f; }

#pragma unroll
        for (int dc = 0; dc < 4; dc++) {
            u32 qf[4][4];
#pragma unroll
            for (int t = 0; t < 4; t++)
                ldsm4(qf[t], aptr(sQ + t * QS, wid * 16, dc * 16, 72, lane));
            u32 n0[4], n1[4];
#pragma unroll
            for (int r = 0; r < 4; r++) {
                n0[r] = qf[0][r] ^ 0x80008000u;
                n1[r] = qf[1][r] ^ 0x80008000u;
            }
#pragma unroll
            for (int nh = 0; nh < 2; nh++) {
                u32 kf[4][8];
#pragma unroll
                for (int t = 0; t < 4; t++) {
                    ldsm4(kf[t],     aptr(sK + t * KS, nh * 32,      dc * 16, 72, lane));
                    ldsm4(kf[t] + 4, aptr(sK + t * KS, nh * 32 + 16, dc * 16, 72, lane));
                }
#pragma unroll
                for (int n4 = 0; n4 < 4; n4++) {
                    int nt = nh * 4 + n4;
                    int i0 = (n4 >> 1) * 4 + (n4 & 1), i1 = i0 + 2;
                    float* cr = sre[nt]; float* ci = sim[nt];
                    mma_(cr, qf[0], kf[0][i0], kf[0][i1]);
                    mma_(cr, qf[0], kf[1][i0], kf[1][i1]);
                    mma_(cr, qf[1], kf[0][i0], kf[0][i1]);
                    mma_(cr, qf[2], kf[2][i0], kf[2][i1]);
                    mma_(cr, qf[2], kf[3][i0], kf[3][i1]);
                    mma_(cr, qf[3], kf[2][i0], kf[2][i1]);
                    mma_(ci, qf[2], kf[0][i0], kf[0][i1]);
                    mma_(ci, qf[2], kf[1][i0], kf[1][i1]);
                    mma_(ci, qf[3], kf[0][i0], kf[0][i1]);
                    mma_(ci, n0,    kf[2][i0], kf[2][i1]);
                    mma_(ci, n0,    kf[3][i0], kf[3][i1]);
                    mma_(ci, n1,    kf[2][i0], kf[2][i1]);
                }
            }
        }

        // ---- p = exp(|s|), register repack S-accum -> P A-frags ----
        u32 ph[4][4], pl[4][4];
#pragma unroll
        for (int kc = 0; kc < 4; kc++) {
            float pv[2][4];
#pragma unroll
            for (int h2 = 0; h2 < 2; h2++) {
                int nt = kc * 2 + h2;
#pragma unroll
                for (int e = 0; e < 4; e++) {
                    float u = sre[nt][e] * sre[nt][e] + sim[nt][e] * sim[nt][e];
                    pv[h2][e] = __expf(__fsqrt_rn(u));
                }
            }
            ls0 += pv[0][0] + pv[0][1] + pv[1][0] + pv[1][1];
            ls1 += pv[0][2] + pv[0][3] + pv[1][2] + pv[1][3];
            split2(pv[0][0], pv[0][1], ph[kc][0], pl[kc][0]);
            split2(pv[0][2], pv[0][3], ph[kc][1], pl[kc][1]);
            split2(pv[1][0], pv[1][1], ph[kc][2], pl[kc][2]);
            split2(pv[1][2], pv[1][3], ph[kc][3], pl[kc][3]);
        }

        // ---- O += P V (hi/lo 3-pass), V via trans ldmatrix ----
#pragma unroll
        for (int kc = 0; kc < 4; kc++)
#pragma unroll
            for (int dh = 0; dh < 2; dh++) {
                u32 vf[4][8];
#pragma unroll
                for (int t = 0; t < 4; t++) {
                    ldsm4t(vf[t],     tptr(sV + t * KS, kc * 16, dh * 32,      72, lane));
                    ldsm4t(vf[t] + 4, tptr(sV + t * KS, kc * 16, dh * 32 + 16, 72, lane));
                }
#pragma unroll
                for (int dt = 0; dt < 4; dt++) {
                    int od = dh * 4 + dt, j0 = dt * 2, j1 = dt * 2 + 1;
                    mma_(o_r[od], ph[kc], vf[0][j0], vf[0][j1]);
                    mma_(o_r[od], ph[kc], vf[1][j0], vf[1][j1]);
                    mma_(o_r[od], pl[kc], vf[0][j0], vf[0][j1]);
                    mma_(o_i[od], ph[kc], vf[2][j0], vf[2][j1]);
                    mma_(o_i[od], ph[kc], vf[3][j0], vf[3][j1]);
                    mma_(o_i[od], pl[kc], vf[2][j0], vf[2][j1]);
                }
            }
        __syncthreads();
    }

    // ---- normalize + write (b, tok, h*64+d) bf16 hi/lo ----
    ls0 += __shfl_xor_sync(0xffffffffu, ls0, 1);
    ls0 += __shfl_xor_sync(0xffffffffu, ls0, 2);
    ls1 += __shfl_xor_sync(0xffffffffu, ls1, 1);
    ls1 += __shfl_xor_sync(0xffffffffu, ls1, 2);
    float inv0 = 1.0f / ls0, inv1 = 1.0f / ls1;

    const int g = lane >> 2, t2 = (lane & 3) * 2;
    const int b = bh >> 3, h = bh & 7;
    const int r0 = q0 + wid * 16 + g;
#pragma unroll
    for (int od = 0; od < 8; od++) {
        int col = h * 64 + od * 8 + t2;
        size_t a0 = ((size_t)(b * NTOK + r0)) * 512 + col;
        size_t a1 = a0 + (size_t)8 * 512;
        u32 rh, rl, ih, il;
        split2(o_r[od][0] * inv0, o_r[od][1] * inv0, rh, rl);
        split2(o_i[od][0] * inv0, o_i[od][1] * inv0, ih, il);
        *(u32*)(aorh + a0) = rh; *(u32*)(aorl + a0) = rl;
        *(u32*)(aoih + a0) = ih; *(u32*)(aoil + a0) = il;
        split2(o_r[od][2] * inv1, o_r[od][3] * inv1, rh, rl);
        split2(o_i[od][2] * inv1, o_i[od][3] * inv1, ih, il);
        *(u32*)(aorh + a1) = rh; *(u32*)(aorl + a1) = rl;
        *(u32*)(aoih + a1) = ih; *(u32*)(aoil + a1) = il;
    }
}

// ---------------------------------------------------------------------------
extern "C" void kernel_launch(void* const* d_in, const int* in_sizes, int n_in,
                              void* d_out, int out_size)
{
    bf *inB, *wB, *qkvB, *aoB;
    cudaGetSymbolAddress((void**)&inB,  g_in);
    cudaGetSymbolAddress((void**)&wB,   g_w);
    cudaGetSymbolAddress((void**)&qkvB, g_qkv);
    cudaGetSymbolAddress((void**)&aoB,  g_ao);

    bf *in_[12], *w_[16], *qkv_[12], *ao_[4];
    for (int t = 0; t < 12; t++) in_[t]  = inB  + (size_t)t * NIN;
    for (int t = 0; t < 16; t++) w_[t]   = wB   + (size_t)t * NW;
    for (int t = 0; t < 12; t++) qkv_[t] = qkvB + (size_t)t * (16 * 2048 * 64);
    for (int t = 0; t < 4;  t++) ao_[t]  = aoB  + (size_t)t * (4096 * 512);

    cudaFuncSetAttribute(cgemm<0>, cudaFuncAttributeMaxDynamicSharedMemorySize, GEMM_SMEM);
    cudaFuncSetAttribute(cgemm<1>, cudaFuncAttributeMaxDynamicSharedMemorySize, GEMM_SMEM);
    cudaFuncSetAttribute(attn,     cudaFuncAttributeMaxDynamicSharedMemorySize, ATTN_SMEM);

    conv_in<<<dim3(NIN / 1024, 6), 256>>>(
        (const float*)d_in[0], (const float*)d_in[1], (const float*)d_in[2],
        (const float*)d_in[3], (const float*)d_in[4], (const float*)d_in[5], inB);
    conv_w<<<dim3(NW / 1024, 8), 256>>>(
        (const float*)d_in[6], (const float*)d_in[7], (const float*)d_in[8],
        (const float*)d_in[9], (const float*)d_in[10], (const float*)d_in[11],
        (const float*)d_in[12], (const float*)d_in[13], wB);

    dim3 gg(8, 32), blk(256);
    cgemm<0><<<gg, blk, GEMM_SMEM>>>(in_[0], in_[1], in_[2], in_[3],
                                     w_[0], w_[1], w_[2], w_[3],
                                     qkv_[0], qkv_[1], qkv_[2], qkv_[3], nullptr);
    cgemm<0><<<gg, blk, GEMM_SMEM>>>(in_[4], in_[5], in_[6], in_[7],
                                     w_[4], w_[5], w_[6], w_[7],
                                     qkv_[4], qkv_[5], qkv_[6], qkv_[7], nullptr);
    cgemm<0><<<gg, blk, GEMM_SMEM>>>(in_[8], in_[9], in_[10], in_[11],
                                     w_[8], w_[9], w_[10], w_[11],
                                     qkv_[8], qkv_[9], qkv_[10], qkv_[11], nullptr);

    attn<<<dim3(16, 16), blk, ATTN_SMEM>>>(
        qkv_[0], qkv_[1], qkv_[2], qkv_[3],
        qkv_[4], qkv_[5], qkv_[6], qkv_[7],
        qkv_[8], qkv_[9], qkv_[10], qkv_[11],
        ao_[0], ao_[1], ao_[2], ao_[3]);

    cgemm<1><<<gg, blk, GEMM_SMEM>>>(ao_[0], ao_[1], ao_[2], ao_[3],
                                     w_[12], w_[13], w_[14], w_[15],
                                     nullptr, nullptr, nullptr, nullptr, (float*)d_out);
}